// round 9
// baseline (speedup 1.0000x reference)
#include <cuda_runtime.h>
#include <cstdint>

#define C 81
#define CC (C * C)
#define TBL 289          // 17x17 (dy,dx) delta table
#define NT 512           // influence block size
#define NITER 13         // ceil(6561/512): 12 full + 1 partial

// Angle table over deltas: g_ang[(dy+8)*17 + (dx+8)]
__device__ float g_ang[TBL];

// Packed per-(center c, point q):
//  .x             = predicate mask bits p in [0,64)
//  .y bits[0:17)  = predicate mask bits p in [64,81)
//  .y bits[32:64) = f32 bit pattern of the distance-based base weight
__device__ ulonglong2 g_pack[CC];

// f32-rounded constants matching JAX weak-typed promotion
__device__ __forceinline__ float rad2deg_f32() { return (float)(180.0 / 3.14159265358979323846); }
__device__ __forceinline__ float maxdist_f32() { return (float)12.727922061357855; }

// ── Kernel A: 289 double-precision atan2s (bit-identical to reference's
//    f32(atan2 double) pipeline), one block, pure latency. ──
__global__ void table_kernel() {
    int i = threadIdx.x;
    if (i < TBL) {
        int r  = i / 17;
        int dy = r - 8;
        int dx = i - r * 17 - 8;
        float t   = (float)atan2(-(double)dy, (double)dx);
        float raw = __fmul_rn(t, rad2deg_f32());
        g_ang[i]  = (raw > 0.0f) ? raw : __fadd_rn(raw, 360.0f);
    }
    asm volatile("griddepcontrol.launch_dependents;" ::: "memory");
}

// ── Kernel B: predicate masks + base weights, no atan2 (table lookups). ──
__global__ void mask_kernel(const int* __restrict__ all_coords) {
    const int c   = blockIdx.x;
    const int tid = threadIdx.x;

    __shared__ int   sy[C], sx[C];
    __shared__ int   sd2[C];
    __shared__ float sang[C];
    __shared__ float stbl[TBL];

    if (tid < C) {
        sy[tid] = all_coords[tid * 3 + 1];
        sx[tid] = all_coords[tid * 3 + 2];
    }

    // g_ang produced by table_kernel
    asm volatile("griddepcontrol.wait;" ::: "memory");
    for (int i = tid; i < TBL; i += blockDim.x) stbl[i] = g_ang[i];
    __syncthreads();

    const int cy = sy[c], cx = sx[c];

    if (tid < C) {
        int dy = sy[tid] - cy;
        int dx = sx[tid] - cx;
        sd2[tid]  = dy * dy + dx * dx;
        sang[tid] = stbl[(dy + 8) * 17 + (dx + 8)];
    }
    __syncthreads();

    if (tid < C) {
        const int   q   = tid;
        const float aq  = sang[q];
        const int   d2q = sd2[q];

        unsigned long long lo = 0ull, hi = 0ull;
        #pragma unroll
        for (int p = 0; p < C; p++) {
            // stable-argsort rank comparison, exact in integers
            int  d2p = sd2[p];
            bool rlt = (d2p < d2q) || (d2p == d2q && p < q);
            // wrapped angular difference, float32 exactly as reference
            float ad = fabsf(__fadd_rn(sang[p], -aq));
            if (ad > 180.0f) ad = __fadd_rn(360.0f, -ad);
            if (rlt && (ad < 45.0f)) {
                if (p < 64) lo |= 1ull << p;
                else        hi |= 1ull << (p - 64);
            }
        }

        float dist = sqrtf((float)d2q);
        float base = __fdiv_rn(__fadd_rn(maxdist_f32(), -dist), maxdist_f32());
        if (base < 0.5f) base = __fmul_rn(base, 0.5f);

        hi |= ((unsigned long long)__float_as_uint(base)) << 32;
        g_pack[c * C + q] = make_ulonglong2(lo, hi);
    }

    asm volatile("griddepcontrol.launch_dependents;" ::: "memory");
}

// ── Kernel C: one block per hypothetical move b. ──
__global__ __launch_bounds__(NT, 1)
void influence_kernel(const float* __restrict__ board,
                      float* __restrict__ out) {
    const int b   = blockIdx.x;
    const int tid = threadIdx.x;

    __shared__ int          s[C];
    __shared__ float        cf[C];       // 1.0 iff center c empty on hypothetical board
    __shared__ signed char  isq[C];      // hypothetical sign at q
    __shared__ unsigned int pos32[3], neg32[3];

    if (tid < C) s[tid] = (int)board[tid];  // exact: board values in {-1,0,1}
    __syncthreads();

    if (s[b] != 0) {                        // non-empty cell: masked to 0 (uniform exit)
        if (tid == 0) out[b] = 0.0f;
        return;
    }

    // Parallel prologue: ballot-built sign masks (warps 0-2, full warps) + factors.
    if (tid < 96) {
        int p = tid;
        int v = (p < C) ? ((p == b) ? 1 : s[p]) : 0;
        unsigned pm = __ballot_sync(0xFFFFFFFFu, v > 0);
        unsigned nm = __ballot_sync(0xFFFFFFFFu, v < 0);
        if ((tid & 31) == 0) { pos32[tid >> 5] = pm; neg32[tid >> 5] = nm; }
    }
    if (tid < C) {
        cf[tid]  = (tid != b && s[tid] == 0) ? 1.0f : 0.0f;
        isq[tid] = (signed char)((tid == b) ? 1 : s[tid]);
    }
    __syncthreads();

    const unsigned long long posLo = pos32[0] | ((unsigned long long)pos32[1] << 32);
    const unsigned long long negLo = neg32[0] | ((unsigned long long)neg32[1] << 32);
    const unsigned           posHi = pos32[2];
    const unsigned           negHi = neg32[2];

    // g_pack produced by mask_kernel
    asm volatile("griddepcontrol.wait;" ::: "memory");

    // Phase 1: stage all loads (MLP ~ 13).
    ulonglong2 mv[NITER];
    #pragma unroll
    for (int i = 0; i < NITER; i++) {
        int idx = tid + i * NT;
        int lidx = (idx < CC) ? idx : 0;
        mv[i] = g_pack[lidx];
    }

    // Phase 2: branch-free accumulate (zero factors kill invalid/empty terms).
    float acc = 0.0f;
    #pragma unroll
    for (int i = 0; i < NITER; i++) {
        int idx = tid + i * NT;
        bool ok = (idx < CC);
        int widx = ok ? idx : 0;
        int c = widx / C;
        int q = widx - c * C;

        int sq = isq[q];
        float f = cf[c] * (float)sq;          // 0 unless (c empty) && (q nonzero)
        if (!ok) f = 0.0f;

        unsigned long long oLo = (sq > 0) ? negLo : posLo;
        unsigned           oHi = (sq > 0) ? negHi : posHi;
        int k = __popcll(mv[i].x & oLo) + __popc((unsigned)mv[i].y & oHi);

        float base = __uint_as_float((unsigned)(mv[i].y >> 32));
        // exp(k*log(0.5)) == 2^-k to ~1e-8 rel; k <= 81 so no underflow
        float w = __int_as_float((unsigned)(127 - k) << 23);
        acc += base * w * f;
    }

    // block reduction: 16 warps
    #pragma unroll
    for (int o = 16; o > 0; o >>= 1)
        acc += __shfl_down_sync(0xFFFFFFFFu, acc, o);

    __shared__ float wsum[NT / 32];
    if ((tid & 31) == 0) wsum[tid >> 5] = acc;
    __syncthreads();
    if (tid == 0) {
        float r = 0.0f;
        #pragma unroll
        for (int w = 0; w < NT / 32; w++) r += wsum[w];
        out[b] = r;
    }
}

static void launch_pdl(const void* fn, dim3 grid, dim3 block, void** args) {
    cudaLaunchConfig_t cfg = {};
    cfg.gridDim  = grid;
    cfg.blockDim = block;
    cfg.dynamicSmemBytes = 0;
    cfg.stream = 0;
    cudaLaunchAttribute attrs[1];
    attrs[0].id = cudaLaunchAttributeProgrammaticStreamSerialization;
    attrs[0].val.programmaticStreamSerializationAllowed = 1;
    cfg.attrs = attrs;
    cfg.numAttrs = 1;
    cudaLaunchKernelExC(&cfg, fn, args);
}

extern "C" void kernel_launch(void* const* d_in, const int* in_sizes, int n_in,
                              void* d_out, int out_size) {
    // all_coords: 81x3 int32 (243 elems); board: 81 float32
    int ci = (in_sizes[0] == 3 * C) ? 0 : 1;
    int bi = 1 - ci;
    const int*   all_coords = (const int*)d_in[ci];
    const float* board      = (const float*)d_in[bi];
    float*       out        = (float*)d_out;

    table_kernel<<<1, 320>>>();

    void* argsB[] = { (void*)&all_coords };
    launch_pdl((const void*)mask_kernel, dim3(C), dim3(128), argsB);

    void* argsC[] = { (void*)&board, (void*)&out };
    launch_pdl((const void*)influence_kernel, dim3(C), dim3(NT), argsC);
}

// round 13
// speedup vs baseline: 1.2056x; 1.2056x over previous
#include <cuda_runtime.h>
#include <cstdint>

#define C 81
#define CC (C * C)
#define TBL 289          // 17x17 (dy,dx) delta table
#define NT 512           // influence block size
#define NITER 13         // ceil(6561/512): 12 full + 1 partial

// Angle table over deltas: g_ang[(dy+8)*17 + (dx+8)]
__device__ float g_ang[TBL];

// Packed per-(center c, point q):
//  .x             = predicate mask bits p in [0,64)
//  .y bits[0:17)  = predicate mask bits p in [64,81)
//  .y bits[32:64) = f32 bit pattern of the distance-based base weight
__device__ ulonglong2 g_pack[CC];

// f32-rounded constants matching JAX weak-typed promotion
__device__ __forceinline__ float rad2deg_f32() { return (float)(180.0 / 3.14159265358979323846); }
__device__ __forceinline__ float maxdist_f32() { return (float)12.727922061357855; }

// ── Kernel A: 289 double-precision atan2s (bit-identical to reference's
//    f32(atan2 double) pipeline). ONE ENTRY PER BLOCK so the FP64 dependency
//    chains run on 289 different SM slots instead of sharing one SM's pipe. ──
__global__ void table_kernel() {
    if (threadIdx.x == 0) {
        int i  = blockIdx.x;
        int r  = i / 17;
        int dy = r - 8;
        int dx = i - r * 17 - 8;
        float t   = (float)atan2(-(double)dy, (double)dx);
        float raw = __fmul_rn(t, rad2deg_f32());
        g_ang[i]  = (raw > 0.0f) ? raw : __fadd_rn(raw, 360.0f);
    }
    asm volatile("griddepcontrol.launch_dependents;" ::: "memory");
}

// ── Kernel B: predicate masks + base weights, no atan2 (table lookups). ──
__global__ void mask_kernel(const int* __restrict__ all_coords) {
    const int c   = blockIdx.x;
    const int tid = threadIdx.x;

    __shared__ int   sy[C], sx[C];
    __shared__ int   sd2[C];
    __shared__ float sang[C];
    __shared__ float stbl[TBL];

    if (tid < C) {
        sy[tid] = all_coords[tid * 3 + 1];
        sx[tid] = all_coords[tid * 3 + 2];
    }

    // g_ang produced by table_kernel
    asm volatile("griddepcontrol.wait;" ::: "memory");
    for (int i = tid; i < TBL; i += blockDim.x) stbl[i] = g_ang[i];
    __syncthreads();

    const int cy = sy[c], cx = sx[c];

    if (tid < C) {
        int dy = sy[tid] - cy;
        int dx = sx[tid] - cx;
        sd2[tid]  = dy * dy + dx * dx;
        sang[tid] = stbl[(dy + 8) * 17 + (dx + 8)];
    }
    __syncthreads();

    if (tid < C) {
        const int   q   = tid;
        const float aq  = sang[q];
        const int   d2q = sd2[q];

        unsigned long long lo = 0ull, hi = 0ull;
        #pragma unroll
        for (int p = 0; p < C; p++) {
            // stable-argsort rank comparison, exact in integers
            int  d2p = sd2[p];
            bool rlt = (d2p < d2q) || (d2p == d2q && p < q);
            // wrapped angular difference, float32 exactly as reference
            float ad = fabsf(__fadd_rn(sang[p], -aq));
            if (ad > 180.0f) ad = __fadd_rn(360.0f, -ad);
            if (rlt && (ad < 45.0f)) {
                if (p < 64) lo |= 1ull << p;
                else        hi |= 1ull << (p - 64);
            }
        }

        float dist = sqrtf((float)d2q);
        float base = __fdiv_rn(__fadd_rn(maxdist_f32(), -dist), maxdist_f32());
        if (base < 0.5f) base = __fmul_rn(base, 0.5f);

        hi |= ((unsigned long long)__float_as_uint(base)) << 32;
        g_pack[c * C + q] = make_ulonglong2(lo, hi);
    }

    asm volatile("griddepcontrol.launch_dependents;" ::: "memory");
}

// ── Kernel C: one block per hypothetical move b. ──
__global__ __launch_bounds__(NT, 1)
void influence_kernel(const float* __restrict__ board,
                      float* __restrict__ out) {
    const int b   = blockIdx.x;
    const int tid = threadIdx.x;

    __shared__ int          s[C];
    __shared__ float        cf[C];       // 1.0 iff center c empty on hypothetical board
    __shared__ signed char  isq[C];      // hypothetical sign at q
    __shared__ unsigned int pos32[3], neg32[3];

    if (tid < C) s[tid] = (int)board[tid];  // exact: board values in {-1,0,1}
    __syncthreads();

    if (s[b] != 0) {                        // non-empty cell: masked to 0 (uniform exit)
        if (tid == 0) out[b] = 0.0f;
        return;
    }

    // Parallel prologue: ballot-built sign masks (warps 0-2, full warps) + factors.
    if (tid < 96) {
        int p = tid;
        int v = (p < C) ? ((p == b) ? 1 : s[p]) : 0;
        unsigned pm = __ballot_sync(0xFFFFFFFFu, v > 0);
        unsigned nm = __ballot_sync(0xFFFFFFFFu, v < 0);
        if ((tid & 31) == 0) { pos32[tid >> 5] = pm; neg32[tid >> 5] = nm; }
    }
    if (tid < C) {
        cf[tid]  = (tid != b && s[tid] == 0) ? 1.0f : 0.0f;
        isq[tid] = (signed char)((tid == b) ? 1 : s[tid]);
    }
    __syncthreads();

    const unsigned long long posLo = pos32[0] | ((unsigned long long)pos32[1] << 32);
    const unsigned long long negLo = neg32[0] | ((unsigned long long)neg32[1] << 32);
    const unsigned           posHi = pos32[2];
    const unsigned           negHi = neg32[2];

    // g_pack produced by mask_kernel
    asm volatile("griddepcontrol.wait;" ::: "memory");

    // Phase 1: stage all loads (MLP ~ 13).
    ulonglong2 mv[NITER];
    #pragma unroll
    for (int i = 0; i < NITER; i++) {
        int idx = tid + i * NT;
        int lidx = (idx < CC) ? idx : 0;
        mv[i] = g_pack[lidx];
    }

    // Phase 2: branch-free accumulate (zero factors kill invalid/empty terms).
    float acc = 0.0f;
    #pragma unroll
    for (int i = 0; i < NITER; i++) {
        int idx = tid + i * NT;
        bool ok = (idx < CC);
        int widx = ok ? idx : 0;
        int c = widx / C;
        int q = widx - c * C;

        int sq = isq[q];
        float f = cf[c] * (float)sq;          // 0 unless (c empty) && (q nonzero)
        if (!ok) f = 0.0f;

        unsigned long long oLo = (sq > 0) ? negLo : posLo;
        unsigned           oHi = (sq > 0) ? negHi : posHi;
        int k = __popcll(mv[i].x & oLo) + __popc((unsigned)mv[i].y & oHi);

        float base = __uint_as_float((unsigned)(mv[i].y >> 32));
        // exp(k*log(0.5)) == 2^-k to ~1e-8 rel; k <= 81 so no underflow
        float w = __int_as_float((unsigned)(127 - k) << 23);
        acc += base * w * f;
    }

    // block reduction: 16 warps
    #pragma unroll
    for (int o = 16; o > 0; o >>= 1)
        acc += __shfl_down_sync(0xFFFFFFFFu, acc, o);

    __shared__ float wsum[NT / 32];
    if ((tid & 31) == 0) wsum[tid >> 5] = acc;
    __syncthreads();
    if (tid == 0) {
        float r = 0.0f;
        #pragma unroll
        for (int w = 0; w < NT / 32; w++) r += wsum[w];
        out[b] = r;
    }
}

static void launch_pdl(const void* fn, dim3 grid, dim3 block, void** args) {
    cudaLaunchConfig_t cfg = {};
    cfg.gridDim  = grid;
    cfg.blockDim = block;
    cfg.dynamicSmemBytes = 0;
    cfg.stream = 0;
    cudaLaunchAttribute attrs[1];
    attrs[0].id = cudaLaunchAttributeProgrammaticStreamSerialization;
    attrs[0].val.programmaticStreamSerializationAllowed = 1;
    cfg.attrs = attrs;
    cfg.numAttrs = 1;
    cudaLaunchKernelExC(&cfg, fn, args);
}

extern "C" void kernel_launch(void* const* d_in, const int* in_sizes, int n_in,
                              void* d_out, int out_size) {
    // all_coords: 81x3 int32 (243 elems); board: 81 float32
    int ci = (in_sizes[0] == 3 * C) ? 0 : 1;
    int bi = 1 - ci;
    const int*   all_coords = (const int*)d_in[ci];
    const float* board      = (const float*)d_in[bi];
    float*       out        = (float*)d_out;

    // One table entry per block: FP64 atan2 chains spread across SMs.
    table_kernel<<<TBL, 32>>>();

    void* argsB[] = { (void*)&all_coords };
    launch_pdl((const void*)mask_kernel, dim3(C), dim3(128), argsB);

    void* argsC[] = { (void*)&board, (void*)&out };
    launch_pdl((const void*)influence_kernel, dim3(C), dim3(NT), argsC);
}